// round 7
// baseline (speedup 1.0000x reference)
#include <cuda_runtime.h>
#include <cstdint>

// Problem constants
#define PB 8
#define PN 8192
#define PM 2048
#define PC 64
#define PS 32
#define OUTC 67              // 3 + 64
#define R2 1.0f

// Scratch (allocation-free rule: __device__ globals)
__device__ int    g_idx[PB * PM * PS];          // 2 MB
__device__ float  g_featT[PB * PN * PC];        // 16 MB, [b][n][c]
__device__ float4 g_xyz4[PB * PN];              // 1 MB, (x,y,z,p2)

// ---------------------------------------------------------------------------
// Kernel 0: pack xyz -> float4 with precomputed p2 — 4 points/thread, LDG.128
// ---------------------------------------------------------------------------
__global__ __launch_bounds__(256) void pack_kernel(const float* __restrict__ xyz)
{
    const int t = blockIdx.x * blockDim.x + threadIdx.x;   // 0 .. B*N/4-1
    if (t >= PB * PN / 4) return;
    const float4* src = (const float4*)(xyz + (size_t)t * 12);
    const float4 a = src[0];
    const float4 b = src[1];
    const float4 c = src[2];

    const float xs[4] = {a.x, a.w, b.z, c.y};
    const float ys[4] = {a.y, b.x, b.w, c.z};
    const float zs[4] = {a.z, b.y, c.x, c.w};

#pragma unroll
    for (int k = 0; k < 4; ++k) {
        const float x = xs[k], y = ys[k], z = zs[k];
        const float p2 = __fadd_rn(__fadd_rn(__fmul_rn(x, x), __fmul_rn(y, y)),
                                   __fmul_rn(z, z));
        g_xyz4[t * 4 + k] = make_float4(x, y, z, p2);
    }
}

// ---------------------------------------------------------------------------
// Kernel 1: transpose (DRAM-bound) + ball query (latency-bound) fused by
// blockIdx — independent inputs, complementary bottlenecks.
// blocks 0..1023   : transpose tiles (32c x 128n, float4 loads)
// blocks 1024..3071: ball query, 8 warps/block, 1 query/warp, 256 pts/iter
// ---------------------------------------------------------------------------
__global__ __launch_bounds__(256) void mid_kernel(
    const float* __restrict__ f, const float* __restrict__ new_xyz)
{
    __shared__ union {
        float4 tile[32][33];      // 16,896 B (transpose path)
        int    slots[8][PS];      //  1,024 B (query path)
    } sm;

    const int bid  = blockIdx.x;
    const int tx   = threadIdx.x & 31;
    const int ty   = threadIdx.x >> 5;     // 0..7

    if (bid < 1024) {
        // ---- transpose path ----
        const int b   = bid >> 7;                 // /128
        const int rem = bid & 127;
        const int c0  = (rem >> 6) << 5;          // 0 or 32
        const int n0  = (rem & 63) << 7;          // 0..8064 step 128

#pragma unroll
        for (int k = 0; k < 4; ++k) {
            const int c = ty + (k << 3);          // 0..31
            const float4* src =
                (const float4*)(f + ((size_t)b * PC + c0 + c) * PN + n0);
            sm.tile[c][tx] = src[tx];
        }
        __syncthreads();

        const float* tf = (const float*)&sm.tile[tx][0];  // 132 floats (c=tx)
#pragma unroll
        for (int i = 0; i < 16; ++i) {
            const int n = (i << 3) + ty;          // 0..127
            g_featT[((size_t)b * PN + n0 + n) * PC + c0 + tx] = tf[n];
        }
    } else {
        // ---- ball query path ----
        const int wid  = (bid - 1024) * 8 + ty;   // global query 0..16383
        const int lane = tx;
        const int b = wid >> 11;
        const int m = wid & (PM - 1);

        const float* q = new_xyz + ((size_t)b * PM + m) * 3;
        const float qx = q[0], qy = q[1], qz = q[2];
        const float q2 = __fadd_rn(__fadd_rn(__fmul_rn(qx, qx), __fmul_rn(qy, qy)),
                                   __fmul_rn(qz, qz));

        int* slot = sm.slots[ty];
        const float4* base4 = g_xyz4 + (size_t)b * PN;
        int cnt = 0;
        for (int n0 = 0; n0 < PN && cnt < PS; n0 += 256) {
            float4 cs[8];
#pragma unroll
            for (int k = 0; k < 8; ++k)
                cs[k] = base4[n0 + (k << 5) + lane];
#pragma unroll
            for (int k = 0; k < 8; ++k) {
                const float4 p = cs[k];
                const float qd = __fadd_rn(__fadd_rn(__fmul_rn(qx, p.x), __fmul_rn(qy, p.y)),
                                           __fmul_rn(qz, p.z));
                const float d2 = __fadd_rn(__fadd_rn(q2, p.w), -__fmul_rn(2.0f, qd));
                const bool valid = d2 < R2;
                const unsigned bal = __ballot_sync(0xffffffffu, valid);
                if (valid) {
                    const int pos = cnt + __popc(bal & ((1u << lane) - 1u));
                    if (pos < PS) slot[pos] = n0 + (k << 5) + lane;
                }
                cnt += __popc(bal);
            }
        }
        __syncwarp();
        const int c = cnt < PS ? cnt : PS;        // >=1 (self point, dist 0)
        const int first = slot[0];
        const int v = (lane < c) ? slot[lane] : first;
        g_idx[(size_t)wid * PS + lane] = v;
    }
}

// ---------------------------------------------------------------------------
// Kernel 2: group v3 — warp per query, smem-staged gather, wide stores
//   Phase B: for sample j (n via shfl), lanes read featT[n][lane], [n][32+lane]
//            (coalesced 128B LDG) -> smem [sample][channel], stride 65
//   Phase C: lane=(g,j): 4 scalar LDS (conflict-free: bank=4j+k+g+ch0) build
//            float4 of samples 4j..4j+3 of channel ch0+g; one STG.128 covers
//            4 channels x 128B = 512B
// ---------------------------------------------------------------------------
__global__ __launch_bounds__(128) void group_kernel(
    const float* __restrict__ new_xyz, float* __restrict__ out)
{
    __shared__ float sf[128 * 65];               // 33,280 B
    const int w    = threadIdx.x >> 5;           // warp in block, 0..3
    const int lane = threadIdx.x & 31;
    const int q    = blockIdx.x * 4 + w;         // global query, 0..16383
    const int b    = q >> 11;
    const int m    = q & (PM - 1);

    // lane j holds neighbor index of sample j
    const int n_reg = g_idx[(size_t)q * PS + lane];

    const float* fb = g_featT + (size_t)b * PN * PC;
    float* srowbase = sf + (size_t)(w * 32) * 65;

#pragma unroll 8
    for (int j = 0; j < 32; ++j) {
        const int n = __shfl_sync(0xffffffffu, n_reg, j);
        const float* src = fb + (size_t)n * PC;
        const float a0 = src[lane];
        const float a1 = src[32 + lane];
        float* dst = srowbase + j * 65;
        dst[lane]      = a0;
        dst[32 + lane] = a1;
    }
    __syncwarp();

    // ---- Phase C ----
    const float* qp = new_xyz + (size_t)q * 3;
    const float qx = qp[0], qy = qp[1], qz = qp[2];
    const float4 p = g_xyz4[(size_t)b * PN + n_reg];

    const size_t chStride = (size_t)PM * PS;     // 65536
    const size_t basep = (size_t)b * OUTC * chStride + (size_t)m * PS + lane;

    // xyz channels: lane = sample (coalesced 128B scalar stores)
    out[basep + 0 * chStride] = p.x - qx;
    out[basep + 1 * chStride] = p.y - qy;
    out[basep + 2 * chStride] = p.z - qz;

    // feature channels: 16 iterations, each = 4 LDS + 1 STG.128
    const int g = lane >> 3;                     // channel-within-quad
    const int j = lane & 7;                      // sample-quad index
    const size_t outbase4 = (size_t)b * OUTC * chStride + (size_t)m * PS + j * 4;

#pragma unroll
    for (int cg = 0; cg < 16; ++cg) {
        const int ch = cg * 4 + g;               // feature channel 0..63
        float4 v;
        v.x = srowbase[(4 * j + 0) * 65 + ch];
        v.y = srowbase[(4 * j + 1) * 65 + ch];
        v.z = srowbase[(4 * j + 2) * 65 + ch];
        v.w = srowbase[(4 * j + 3) * 65 + ch];
        *(float4*)(out + outbase4 + (size_t)(3 + ch) * chStride) = v;
    }
}

// ---------------------------------------------------------------------------
extern "C" void kernel_launch(void* const* d_in, const int* in_sizes, int n_in,
                              void* d_out, int out_size)
{
    const float* xyz   = nullptr;
    const float* nxyz  = nullptr;
    const float* feats = nullptr;
    for (int i = 0; i < n_in; ++i) {
        if      (in_sizes[i] == PB * PN * 3) xyz   = (const float*)d_in[i];
        else if (in_sizes[i] == PB * PM * 3) nxyz  = (const float*)d_in[i];
        else if (in_sizes[i] == PB * PC * PN) feats = (const float*)d_in[i];
    }
    float* out = (float*)d_out;
    (void)out_size;

    pack_kernel<<<(PB * PN / 4 + 255) / 256, 256>>>(xyz);
    mid_kernel<<<1024 + 2048, 256>>>(feats, nxyz);        // transpose ∥ ball query
    group_kernel<<<(PB * PM) / 4, 128>>>(nxyz, out);
}

// round 8
// speedup vs baseline: 1.0405x; 1.0405x over previous
#include <cuda_runtime.h>
#include <cstdint>

// Problem constants
#define PB 8
#define PN 8192
#define PM 2048
#define PC 64
#define PS 32
#define OUTC 67              // 3 + 64
#define R2 1.0f

// Scratch (allocation-free rule: __device__ globals)
__device__ int    g_idx[PB * PM * PS];          // 2 MB
__device__ float  g_featT[PB * PN * PC];        // 16 MB, [b][n][c]
__device__ float4 g_xyz4[PB * PN];              // 1 MB, (x,y,z,p2)

// ---------------------------------------------------------------------------
// Kernel 0: pack xyz -> float4 with precomputed p2 (reference rounding)
// ---------------------------------------------------------------------------
__global__ __launch_bounds__(256) void pack_kernel(const float* __restrict__ xyz)
{
    const int i = blockIdx.x * blockDim.x + threadIdx.x;   // 0 .. B*N-1
    if (i >= PB * PN) return;
    const float x = xyz[i * 3 + 0];
    const float y = xyz[i * 3 + 1];
    const float z = xyz[i * 3 + 2];
    const float p2 = __fadd_rn(__fadd_rn(__fmul_rn(x, x), __fmul_rn(y, y)),
                               __fmul_rn(z, z));
    g_xyz4[i] = make_float4(x, y, z, p2);
}

// ---------------------------------------------------------------------------
// Kernel 1: transpose (DRAM-bound) + ball query (latency-bound) fused by
// blockIdx — independent inputs, complementary bottlenecks.
// blocks 0..1023   : transpose tiles (32c x 128n, float4 loads)
// blocks 1024..3071: ball query, 8 warps/block, 1 query/warp, 256 pts/iter
// ---------------------------------------------------------------------------
__global__ __launch_bounds__(256) void mid_kernel(
    const float* __restrict__ f, const float* __restrict__ new_xyz)
{
    __shared__ union {
        float4 tile[32][33];      // 16,896 B (transpose path)
        int    slots[8][PS];      //  1,024 B (query path)
    } sm;

    const int bid  = blockIdx.x;
    const int tx   = threadIdx.x & 31;
    const int ty   = threadIdx.x >> 5;     // 0..7

    if (bid < 1024) {
        // ---- transpose path ----
        const int b   = bid >> 7;                 // /128
        const int rem = bid & 127;
        const int c0  = (rem >> 6) << 5;          // 0 or 32
        const int n0  = (rem & 63) << 7;          // 0..8064 step 128

#pragma unroll
        for (int k = 0; k < 4; ++k) {
            const int c = ty + (k << 3);          // 0..31
            const float4* src =
                (const float4*)(f + ((size_t)b * PC + c0 + c) * PN + n0);
            sm.tile[c][tx] = src[tx];
        }
        __syncthreads();

        const float* tf = (const float*)&sm.tile[tx][0];  // 132 floats (c=tx)
#pragma unroll
        for (int i = 0; i < 16; ++i) {
            const int n = (i << 3) + ty;          // 0..127
            g_featT[((size_t)b * PN + n0 + n) * PC + c0 + tx] = tf[n];
        }
    } else {
        // ---- ball query path ----
        const int wid  = (bid - 1024) * 8 + ty;   // global query 0..16383
        const int lane = tx;
        const int b = wid >> 11;
        const int m = wid & (PM - 1);

        const float* q = new_xyz + ((size_t)b * PM + m) * 3;
        const float qx = q[0], qy = q[1], qz = q[2];
        const float q2 = __fadd_rn(__fadd_rn(__fmul_rn(qx, qx), __fmul_rn(qy, qy)),
                                   __fmul_rn(qz, qz));

        int* slot = sm.slots[ty];
        const float4* base4 = g_xyz4 + (size_t)b * PN;
        int cnt = 0;
        for (int n0 = 0; n0 < PN && cnt < PS; n0 += 256) {
            float4 cs[8];
#pragma unroll
            for (int k = 0; k < 8; ++k)
                cs[k] = base4[n0 + (k << 5) + lane];
#pragma unroll
            for (int k = 0; k < 8; ++k) {
                const float4 p = cs[k];
                const float qd = __fadd_rn(__fadd_rn(__fmul_rn(qx, p.x), __fmul_rn(qy, p.y)),
                                           __fmul_rn(qz, p.z));
                const float d2 = __fadd_rn(__fadd_rn(q2, p.w), -__fmul_rn(2.0f, qd));
                const bool valid = d2 < R2;
                const unsigned bal = __ballot_sync(0xffffffffu, valid);
                if (valid) {
                    const int pos = cnt + __popc(bal & ((1u << lane) - 1u));
                    if (pos < PS) slot[pos] = n0 + (k << 5) + lane;
                }
                cnt += __popc(bal);
            }
        }
        __syncwarp();
        const int c = cnt < PS ? cnt : PS;        // >=1 (self point, dist 0)
        const int first = slot[0];
        const int v = (lane < c) ? slot[lane] : first;
        g_idx[(size_t)wid * PS + lane] = v;
    }
}

// ---------------------------------------------------------------------------
// Kernel 2: group v4 — warp per query, float4 end-to-end
//   smem layout: sm4[warp][cg * 33 + sample]  (cg = channel quad 0..15)
//   Phase B: 16 iters; lane cg=lane&15, sample=2*it+(lane>>4);
//            1 LDG.128 (256B/row, 2 rows per instr) + 1 STS.128. Banks
//            (4cg+4j) mod 32 distinct within 8-lane phase -> conflict-free.
//   Phase C: lane = sample; 16x LDS.128 (banks 4cg+4s, conflict-free) +
//            4 coalesced 128B scalar STG each.
// ---------------------------------------------------------------------------
__global__ __launch_bounds__(128) void group_kernel(
    const float* __restrict__ new_xyz, float* __restrict__ out)
{
    __shared__ float4 sf4[4][16 * 33];           // 33,792 B
    const int w    = threadIdx.x >> 5;           // warp in block, 0..3
    const int lane = threadIdx.x & 31;
    const int q    = blockIdx.x * 4 + w;         // global query, 0..16383
    const int b    = q >> 11;
    const int m    = q & (PM - 1);

    // lane j holds neighbor index of sample j
    const int n_reg = g_idx[(size_t)q * PS + lane];

    const float4* fb4 = (const float4*)(g_featT + (size_t)b * PN * PC);
    float4* sm4 = sf4[w];

    const int cg   = lane & 15;                  // channel quad handled by lane
    const int half = lane >> 4;                  // 0 or 1: sample parity

#pragma unroll
    for (int it = 0; it < 16; ++it) {
        const int j = (it << 1) | half;          // sample 0..31
        const int n = __shfl_sync(0xffffffffu, n_reg, j);
        const float4 v = fb4[(size_t)n * 16 + cg];       // LDG.128, coalesced
        sm4[cg * 33 + j] = v;                            // STS.128, conflict-free
    }
    __syncwarp();

    // ---- Phase C: lane = sample slot ----
    const float* qp = new_xyz + (size_t)q * 3;
    const float qx = qp[0], qy = qp[1], qz = qp[2];
    const float4 p = g_xyz4[(size_t)b * PN + n_reg];

    const size_t chStride = (size_t)PM * PS;     // 65536
    const size_t basep = (size_t)b * OUTC * chStride + (size_t)m * PS + lane;

    out[basep + 0 * chStride] = p.x - qx;
    out[basep + 1 * chStride] = p.y - qy;
    out[basep + 2 * chStride] = p.z - qz;

    float* o = out + basep + 3 * chStride;
#pragma unroll
    for (int c4 = 0; c4 < 16; ++c4) {
        const float4 v = sm4[c4 * 33 + lane];            // LDS.128, conflict-free
        o[0 * chStride] = v.x;
        o[1 * chStride] = v.y;
        o[2 * chStride] = v.z;
        o[3 * chStride] = v.w;
        o += 4 * chStride;
    }
}

// ---------------------------------------------------------------------------
extern "C" void kernel_launch(void* const* d_in, const int* in_sizes, int n_in,
                              void* d_out, int out_size)
{
    const float* xyz   = nullptr;
    const float* nxyz  = nullptr;
    const float* feats = nullptr;
    for (int i = 0; i < n_in; ++i) {
        if      (in_sizes[i] == PB * PN * 3) xyz   = (const float*)d_in[i];
        else if (in_sizes[i] == PB * PM * 3) nxyz  = (const float*)d_in[i];
        else if (in_sizes[i] == PB * PC * PN) feats = (const float*)d_in[i];
    }
    float* out = (float*)d_out;
    (void)out_size;

    pack_kernel<<<(PB * PN + 255) / 256, 256>>>(xyz);
    mid_kernel<<<1024 + 2048, 256>>>(feats, nxyz);        // transpose ∥ ball query
    group_kernel<<<(PB * PM) / 4, 128>>>(nxyz, out);
}

// round 9
// speedup vs baseline: 1.0710x; 1.0293x over previous
#include <cuda_runtime.h>
#include <cstdint>

// Problem constants
#define PB 8
#define PN 8192
#define PM 2048
#define PC 64
#define PS 32
#define OUTC 67              // 3 + 64
#define R2 1.0f

// Scratch (allocation-free rule: __device__ globals)
__device__ int    g_idx[PB * PM * PS];          // 2 MB
__device__ float  g_featT[PB * PN * PC];        // 16 MB, [b][n][c]
__device__ float4 g_xyz4[PB * PN];              // 1 MB, (x,y,z,p2)

// ---------------------------------------------------------------------------
// Kernel 0: pack xyz -> float4 with precomputed p2 (reference rounding)
// ---------------------------------------------------------------------------
__global__ __launch_bounds__(256) void pack_kernel(const float* __restrict__ xyz)
{
    const int i = blockIdx.x * blockDim.x + threadIdx.x;   // 0 .. B*N-1
    if (i >= PB * PN) return;
    const float x = xyz[i * 3 + 0];
    const float y = xyz[i * 3 + 1];
    const float z = xyz[i * 3 + 2];
    const float p2 = __fadd_rn(__fadd_rn(__fmul_rn(x, x), __fmul_rn(y, y)),
                               __fmul_rn(z, z));
    g_xyz4[i] = make_float4(x, y, z, p2);
}

// ---------------------------------------------------------------------------
// Kernel 1: transpose (DRAM-bound) + ball query (latency-bound) fused by
// blockIdx — independent inputs, complementary bottlenecks.
// blocks 0..1023   : transpose tiles (32c x 128n, float4 loads)
// blocks 1024..3071: ball query, 8 warps/block, 1 query/warp, 256 pts/iter
// ---------------------------------------------------------------------------
__global__ __launch_bounds__(256) void mid_kernel(
    const float* __restrict__ f, const float* __restrict__ new_xyz)
{
    __shared__ union {
        float4 tile[32][33];      // 16,896 B (transpose path)
        int    slots[8][PS];      //  1,024 B (query path)
    } sm;

    const int bid  = blockIdx.x;
    const int tx   = threadIdx.x & 31;
    const int ty   = threadIdx.x >> 5;     // 0..7

    if (bid < 1024) {
        // ---- transpose path ----
        const int b   = bid >> 7;                 // /128
        const int rem = bid & 127;
        const int c0  = (rem >> 6) << 5;          // 0 or 32
        const int n0  = (rem & 63) << 7;          // 0..8064 step 128

#pragma unroll
        for (int k = 0; k < 4; ++k) {
            const int c = ty + (k << 3);          // 0..31
            const float4* src =
                (const float4*)(f + ((size_t)b * PC + c0 + c) * PN + n0);
            sm.tile[c][tx] = src[tx];
        }
        __syncthreads();

        const float* tf = (const float*)&sm.tile[tx][0];  // 132 floats (c=tx)
#pragma unroll
        for (int i = 0; i < 16; ++i) {
            const int n = (i << 3) + ty;          // 0..127
            g_featT[((size_t)b * PN + n0 + n) * PC + c0 + tx] = tf[n];
        }
    } else {
        // ---- ball query path ----
        const int wid  = (bid - 1024) * 8 + ty;   // global query 0..16383
        const int lane = tx;
        const int b = wid >> 11;
        const int m = wid & (PM - 1);

        const float* q = new_xyz + ((size_t)b * PM + m) * 3;
        const float qx = q[0], qy = q[1], qz = q[2];
        const float q2 = __fadd_rn(__fadd_rn(__fmul_rn(qx, qx), __fmul_rn(qy, qy)),
                                   __fmul_rn(qz, qz));

        int* slot = sm.slots[ty];
        const float4* base4 = g_xyz4 + (size_t)b * PN;
        int cnt = 0;
        for (int n0 = 0; n0 < PN && cnt < PS; n0 += 256) {
            float4 cs[8];
#pragma unroll
            for (int k = 0; k < 8; ++k)
                cs[k] = base4[n0 + (k << 5) + lane];
#pragma unroll
            for (int k = 0; k < 8; ++k) {
                const float4 p = cs[k];
                const float qd = __fadd_rn(__fadd_rn(__fmul_rn(qx, p.x), __fmul_rn(qy, p.y)),
                                           __fmul_rn(qz, p.z));
                const float d2 = __fadd_rn(__fadd_rn(q2, p.w), -__fmul_rn(2.0f, qd));
                const bool valid = d2 < R2;
                const unsigned bal = __ballot_sync(0xffffffffu, valid);
                if (valid) {
                    const int pos = cnt + __popc(bal & ((1u << lane) - 1u));
                    if (pos < PS) slot[pos] = n0 + (k << 5) + lane;
                }
                cnt += __popc(bal);
            }
        }
        __syncwarp();
        const int c = cnt < PS ? cnt : PS;        // >=1 (self point, dist 0)
        const int first = slot[0];
        const int v = (lane < c) ? slot[lane] : first;
        g_idx[(size_t)wid * PS + lane] = v;
    }
}

// ---------------------------------------------------------------------------
// Kernel 2: group v5 — warp per query, 2-pass channel halves (occupancy 2.2x)
//   Pass h covers channel quads 8h..8h+7 (= the h-th 128B half of each row).
//   Phase B: 8 iters; lane cg=lane&7 (+8h), sample=4*it+(lane>>3);
//            1 LDG.128 (4 samples x 128B half-row = 4 full lines) + STS.128.
//   Phase C: lane = sample; 8x LDS.128 + 4 coalesced scalar STG each.
//   smem 16.9 KB/block -> ~13 blocks/SM -> 52 warps resident.
// ---------------------------------------------------------------------------
__global__ __launch_bounds__(128) void group_kernel(
    const float* __restrict__ new_xyz, float* __restrict__ out)
{
    __shared__ float4 sf4[4][8 * 33];            // 16,896 B
    const int w    = threadIdx.x >> 5;           // warp in block, 0..3
    const int lane = threadIdx.x & 31;
    const int q    = blockIdx.x * 4 + w;         // global query, 0..16383
    const int b    = q >> 11;
    const int m    = q & (PM - 1);

    // lane j holds neighbor index of sample j
    const int n_reg = g_idx[(size_t)q * PS + lane];

    const float4* fb4 = (const float4*)(g_featT + (size_t)b * PN * PC);
    float4* sm4 = sf4[w];

    // ---- xyz channels (once) ----
    const float* qp = new_xyz + (size_t)q * 3;
    const float qx = qp[0], qy = qp[1], qz = qp[2];
    const float4 p = g_xyz4[(size_t)b * PN + n_reg];

    const size_t chStride = (size_t)PM * PS;     // 65536
    const size_t basep = (size_t)b * OUTC * chStride + (size_t)m * PS + lane;

    out[basep + 0 * chStride] = p.x - qx;
    out[basep + 1 * chStride] = p.y - qy;
    out[basep + 2 * chStride] = p.z - qz;

    const int cg  = lane & 7;                    // quad within half
    const int grp = lane >> 3;                   // 0..3: sample subgroup

#pragma unroll
    for (int h = 0; h < 2; ++h) {
        // ---- Phase B: gather half h ----
#pragma unroll
        for (int it = 0; it < 8; ++it) {
            const int j = (it << 2) | grp;       // sample 0..31
            const int n = __shfl_sync(0xffffffffu, n_reg, j);
            const float4 v = fb4[(size_t)n * 16 + (h << 3) + cg];  // LDG.128
            sm4[cg * 33 + j] = v;                                   // STS.128
        }
        __syncwarp();

        // ---- Phase C: store half h (lane = sample) ----
        float* o = out + basep + (size_t)(3 + (h << 5)) * chStride;
#pragma unroll
        for (int c4 = 0; c4 < 8; ++c4) {
            const float4 v = sm4[c4 * 33 + lane];                   // LDS.128
            o[0 * chStride] = v.x;
            o[1 * chStride] = v.y;
            o[2 * chStride] = v.z;
            o[3 * chStride] = v.w;
            o += 4 * chStride;
        }
        __syncwarp();
    }
}

// ---------------------------------------------------------------------------
extern "C" void kernel_launch(void* const* d_in, const int* in_sizes, int n_in,
                              void* d_out, int out_size)
{
    const float* xyz   = nullptr;
    const float* nxyz  = nullptr;
    const float* feats = nullptr;
    for (int i = 0; i < n_in; ++i) {
        if      (in_sizes[i] == PB * PN * 3) xyz   = (const float*)d_in[i];
        else if (in_sizes[i] == PB * PM * 3) nxyz  = (const float*)d_in[i];
        else if (in_sizes[i] == PB * PC * PN) feats = (const float*)d_in[i];
    }
    float* out = (float*)d_out;
    (void)out_size;

    pack_kernel<<<(PB * PN + 255) / 256, 256>>>(xyz);
    mid_kernel<<<1024 + 2048, 256>>>(feats, nxyz);        // transpose ∥ ball query
    group_kernel<<<(PB * PM) / 4, 128>>>(nxyz, out);
}

// round 10
// speedup vs baseline: 1.0725x; 1.0014x over previous
#include <cuda_runtime.h>
#include <cstdint>

// Problem constants
#define PB 8
#define PN 8192
#define PM 2048
#define PC 64
#define PS 32
#define OUTC 67              // 3 + 64
#define R2 1.0f

// Scratch (allocation-free rule: __device__ globals)
__device__ int    g_idx[PB * PM * PS];          // 2 MB
__device__ float  g_featT[PB * PN * PC];        // 16 MB, [b][n][c]

// ---------------------------------------------------------------------------
// Kernel 1: transpose (DRAM-bound) + ball query (latency-bound) fused by
// blockIdx — independent inputs, complementary bottlenecks.
// blocks 0..1023   : transpose tiles (32c x 128n, float4 loads)
// blocks 1024..3071: ball query, 8 warps/block, 1 query/warp, 256 pts/iter
//                    reads RAW xyz (L2-resident), p2 computed inline
// ---------------------------------------------------------------------------
__global__ __launch_bounds__(256) void mid_kernel(
    const float* __restrict__ f, const float* __restrict__ xyz,
    const float* __restrict__ new_xyz)
{
    __shared__ union {
        float4 tile[32][33];      // 16,896 B (transpose path)
        int    slots[8][PS];      //  1,024 B (query path)
    } sm;

    const int bid  = blockIdx.x;
    const int tx   = threadIdx.x & 31;
    const int ty   = threadIdx.x >> 5;     // 0..7

    if (bid < 1024) {
        // ---- transpose path ----
        const int b   = bid >> 7;                 // /128
        const int rem = bid & 127;
        const int c0  = (rem >> 6) << 5;          // 0 or 32
        const int n0  = (rem & 63) << 7;          // 0..8064 step 128

#pragma unroll
        for (int k = 0; k < 4; ++k) {
            const int c = ty + (k << 3);          // 0..31
            const float4* src =
                (const float4*)(f + ((size_t)b * PC + c0 + c) * PN + n0);
            sm.tile[c][tx] = src[tx];
        }
        __syncthreads();

        const float* tf = (const float*)&sm.tile[tx][0];  // 132 floats (c=tx)
#pragma unroll
        for (int i = 0; i < 16; ++i) {
            const int n = (i << 3) + ty;          // 0..127
            g_featT[((size_t)b * PN + n0 + n) * PC + c0 + tx] = tf[n];
        }
    } else {
        // ---- ball query path ----
        const int wid  = (bid - 1024) * 8 + ty;   // global query 0..16383
        const int lane = tx;
        const int b = wid >> 11;
        const int m = wid & (PM - 1);

        const float* q = new_xyz + ((size_t)b * PM + m) * 3;
        const float qx = q[0], qy = q[1], qz = q[2];
        const float q2 = __fadd_rn(__fadd_rn(__fmul_rn(qx, qx), __fmul_rn(qy, qy)),
                                   __fmul_rn(qz, qz));

        int* slot = sm.slots[ty];
        const float* xb = xyz + (size_t)b * PN * 3;
        int cnt = 0;
        for (int n0 = 0; n0 < PN && cnt < PS; n0 += 256) {
            float px[8], py[8], pz[8];
            const float* s = xb + (size_t)(n0 + lane) * 3;
#pragma unroll
            for (int k = 0; k < 8; ++k) {          // 24 independent loads, MLP
                px[k] = s[k * 96 + 0];
                py[k] = s[k * 96 + 1];
                pz[k] = s[k * 96 + 2];
            }
#pragma unroll
            for (int k = 0; k < 8; ++k) {
                const float p2 = __fadd_rn(__fadd_rn(__fmul_rn(px[k], px[k]),
                                                     __fmul_rn(py[k], py[k])),
                                           __fmul_rn(pz[k], pz[k]));
                const float qd = __fadd_rn(__fadd_rn(__fmul_rn(qx, px[k]),
                                                     __fmul_rn(qy, py[k])),
                                           __fmul_rn(qz, pz[k]));
                const float d2 = __fadd_rn(__fadd_rn(q2, p2), -__fmul_rn(2.0f, qd));
                const bool valid = d2 < R2;
                const unsigned bal = __ballot_sync(0xffffffffu, valid);
                if (valid) {
                    const int pos = cnt + __popc(bal & ((1u << lane) - 1u));
                    if (pos < PS) slot[pos] = n0 + (k << 5) + lane;
                }
                cnt += __popc(bal);
            }
        }
        __syncwarp();
        const int c = cnt < PS ? cnt : PS;        // >=1 (self point, dist 0)
        const int first = slot[0];
        const int v = (lane < c) ? slot[lane] : first;
        g_idx[(size_t)wid * PS + lane] = v;
    }
}

// ---------------------------------------------------------------------------
// Kernel 2: group v6 — warp per query, 2-pass channel halves, streaming stores
//   __stcs on all output writes: keep featT L2-resident for the gather,
//   let the 140MB write stream pass through evict-first.
// ---------------------------------------------------------------------------
__global__ __launch_bounds__(128) void group_kernel(
    const float* __restrict__ xyz, const float* __restrict__ new_xyz,
    float* __restrict__ out)
{
    __shared__ float4 sf4[4][8 * 33];            // 16,896 B
    const int w    = threadIdx.x >> 5;           // warp in block, 0..3
    const int lane = threadIdx.x & 31;
    const int q    = blockIdx.x * 4 + w;         // global query, 0..16383
    const int b    = q >> 11;
    const int m    = q & (PM - 1);

    // lane j holds neighbor index of sample j
    const int n_reg = g_idx[(size_t)q * PS + lane];

    const float4* fb4 = (const float4*)(g_featT + (size_t)b * PN * PC);
    float4* sm4 = sf4[w];

    // ---- xyz channels (once) ----
    const float* qp = new_xyz + (size_t)q * 3;
    const float qx = qp[0], qy = qp[1], qz = qp[2];
    const float* pp = xyz + ((size_t)b * PN + n_reg) * 3;   // L2-resident
    const float px = pp[0], py = pp[1], pz = pp[2];

    const size_t chStride = (size_t)PM * PS;     // 65536
    const size_t basep = (size_t)b * OUTC * chStride + (size_t)m * PS + lane;

    __stcs(out + basep + 0 * chStride, px - qx);
    __stcs(out + basep + 1 * chStride, py - qy);
    __stcs(out + basep + 2 * chStride, pz - qz);

    const int cg  = lane & 7;                    // quad within half
    const int grp = lane >> 3;                   // 0..3: sample subgroup

#pragma unroll
    for (int h = 0; h < 2; ++h) {
        // ---- Phase B: gather half h ----
#pragma unroll
        for (int it = 0; it < 8; ++it) {
            const int j = (it << 2) | grp;       // sample 0..31
            const int n = __shfl_sync(0xffffffffu, n_reg, j);
            const float4 v = fb4[(size_t)n * 16 + (h << 3) + cg];  // LDG.128
            sm4[cg * 33 + j] = v;                                   // STS.128
        }
        __syncwarp();

        // ---- Phase C: store half h (lane = sample) ----
        float* o = out + basep + (size_t)(3 + (h << 5)) * chStride;
#pragma unroll
        for (int c4 = 0; c4 < 8; ++c4) {
            const float4 v = sm4[c4 * 33 + lane];                   // LDS.128
            __stcs(o + 0 * chStride, v.x);
            __stcs(o + 1 * chStride, v.y);
            __stcs(o + 2 * chStride, v.z);
            __stcs(o + 3 * chStride, v.w);
            o += 4 * chStride;
        }
        __syncwarp();
    }
}

// ---------------------------------------------------------------------------
extern "C" void kernel_launch(void* const* d_in, const int* in_sizes, int n_in,
                              void* d_out, int out_size)
{
    const float* xyz   = nullptr;
    const float* nxyz  = nullptr;
    const float* feats = nullptr;
    for (int i = 0; i < n_in; ++i) {
        if      (in_sizes[i] == PB * PN * 3) xyz   = (const float*)d_in[i];
        else if (in_sizes[i] == PB * PM * 3) nxyz  = (const float*)d_in[i];
        else if (in_sizes[i] == PB * PC * PN) feats = (const float*)d_in[i];
    }
    float* out = (float*)d_out;
    (void)out_size;

    mid_kernel<<<1024 + 2048, 256>>>(feats, xyz, nxyz);   // transpose ∥ ball query
    group_kernel<<<(PB * PM) / 4, 128>>>(xyz, nxyz, out);
}